// round 1
// baseline (speedup 1.0000x reference)
#include <cuda_runtime.h>
#include <cuda_bf16.h>
#include <math.h>

// Problem shape (fixed by dataset): N=500000, D=128, K=2048
#define MAXN   500000
#define DIM    128
#define NBINS  65536
#define CAP    4096   // candidate capacity (expected ~2150)
#define SORTN  4096
#define MAXK   2048

static __device__ unsigned int        g_keys[MAXN];
static __device__ unsigned int        g_hist[NBINS];
static __device__ unsigned int        g_counter;
static __device__ unsigned int        g_thresh;
static __device__ unsigned long long  g_cand[CAP];
static __device__ unsigned long long  g_topk[MAXK];

// order-preserving float -> u32 key
__device__ __forceinline__ unsigned int fkey(float f) {
    unsigned int b = __float_as_uint(f);
    return (b & 0x80000000u) ? ~b : (b | 0x80000000u);
}
__device__ __forceinline__ float fdec(unsigned int k) {
    unsigned int b = (k & 0x80000000u) ? (k ^ 0x80000000u) : ~k;
    return __uint_as_float(b);
}

// ---------------------------------------------------------------- kernel 1
__global__ void zero_kernel() {
    int i = blockIdx.x * blockDim.x + threadIdx.x;   // <<<256,256>>> = 65536
    g_hist[i] = 0u;
    if (i == 0) g_counter = 0u;
}

// ---------------------------------------------------------------- kernel 2
// warp-per-row scoring: y = (x_row . p) / ||p||; key -> g_keys, histogram
__global__ void score_kernel(const float* __restrict__ x,
                             const float* __restrict__ p, int n) {
    int lane = threadIdx.x & 31;
    int row  = (blockIdx.x * blockDim.x + threadIdx.x) >> 5;

    float4 p4 = reinterpret_cast<const float4*>(p)[lane];
    float sq = p4.x * p4.x + p4.y * p4.y + p4.z * p4.z + p4.w * p4.w;
    #pragma unroll
    for (int off = 16; off > 0; off >>= 1)
        sq += __shfl_xor_sync(0xFFFFFFFFu, sq, off);
    float inv = 1.0f / sqrtf(sq);

    if (row >= n) return;
    float4 x4 = reinterpret_cast<const float4*>(x)[(size_t)row * 32 + lane];
    float d = x4.x * p4.x + x4.y * p4.y + x4.z * p4.z + x4.w * p4.w;
    #pragma unroll
    for (int off = 16; off > 0; off >>= 1)
        d += __shfl_xor_sync(0xFFFFFFFFu, d, off);

    if (lane == 0) {
        float y = d * inv;
        unsigned int key = fkey(y);
        g_keys[row] = key;
        atomicAdd(&g_hist[key >> 16], 1u);
    }
}

// ---------------------------------------------------------------- kernel 3
// find smallest bin b such that count(key >= b<<16) >= kk
__global__ void thresh_kernel(int kk) {
    __shared__ unsigned int csum[256];
    __shared__ unsigned int cbin[256];
    __shared__ int schunk;
    __shared__ unsigned int sabove;
    int t = threadIdx.x;

    unsigned int s = 0;
    #pragma unroll 8
    for (int i = 0; i < 256; i++) s += g_hist[t * 256 + i];
    csum[t] = s;
    __syncthreads();

    if (t == 0) {
        unsigned int cum = 0; int ch = 0;
        for (int c = 255; c >= 0; c--) {
            unsigned int nc = cum + csum[c];
            if (nc >= (unsigned int)kk) { ch = c; sabove = cum; break; }
            cum = nc;
        }
        schunk = ch;
    }
    __syncthreads();

    int ch = schunk;
    cbin[t] = g_hist[ch * 256 + t];
    __syncthreads();

    if (t == 0) {
        unsigned int cum = sabove;
        int b = ch * 256;
        for (int i = 255; i >= 0; i--) {
            cum += cbin[i];
            if (cum >= (unsigned int)kk) { b = ch * 256 + i; break; }
        }
        g_thresh = ((unsigned int)b) << 16;
    }
}

// ---------------------------------------------------------------- kernel 4
__global__ void compact_kernel(int n) {
    unsigned int thr = g_thresh;
    int stride = gridDim.x * blockDim.x;
    for (int i = blockIdx.x * blockDim.x + threadIdx.x; i < n; i += stride) {
        unsigned int key = g_keys[i];
        if (key >= thr) {
            unsigned int pos = atomicAdd(&g_counter, 1u);
            if (pos < CAP)
                g_cand[pos] = ((unsigned long long)key << 32) |
                              (unsigned long long)(0xFFFFFFFFu - (unsigned int)i);
        }
    }
}

// ---------------------------------------------------------------- kernel 5
// single-block bitonic sort, descending, 4096 u64 in shared
__global__ void sort_kernel(int kk) {
    __shared__ unsigned long long s[SORTN];
    int tid = threadIdx.x;                       // 1024 threads
    unsigned int C = g_counter; if (C > CAP) C = CAP;

    for (int i = tid; i < SORTN; i += 1024)
        s[i] = (i < (int)C) ? g_cand[i] : 0ULL;
    __syncthreads();

    for (int ks = 2; ks <= SORTN; ks <<= 1) {
        for (int j = ks >> 1; j > 0; j >>= 1) {
            for (int i = tid; i < SORTN; i += 1024) {
                int l = i ^ j;
                if (l > i) {
                    unsigned long long a = s[i], b = s[l];
                    bool desc = ((i & ks) == 0);
                    bool sw = desc ? (a < b) : (a > b);
                    if (sw) { s[i] = b; s[l] = a; }
                }
            }
            __syncthreads();
        }
    }
    for (int i = tid; i < kk; i += 1024) g_topk[i] = s[i];
}

// ---------------------------------------------------------------- kernel 6
// out[j] = x[idx_j] * tanh(y_j) ; <<<kk, 128>>>
__global__ void gather_kernel(const float* __restrict__ x,
                              float* __restrict__ out) {
    unsigned long long e = g_topk[blockIdx.x];
    unsigned int key = (unsigned int)(e >> 32);
    unsigned int idx = 0xFFFFFFFFu - (unsigned int)(e & 0xFFFFFFFFull);
    float tv = tanhf(fdec(key));
    size_t src = (size_t)idx * DIM + threadIdx.x;
    size_t dst = (size_t)blockIdx.x * DIM + threadIdx.x;
    out[dst] = x[src] * tv;
}

// ----------------------------------------------------------------
extern "C" void kernel_launch(void* const* d_in, const int* in_sizes, int n_in,
                              void* d_out, int out_size) {
    const float* x = (const float*)d_in[0];
    const float* p = (const float*)d_in[1];
    float* out = (float*)d_out;

    int n  = in_sizes[0] / DIM;      // 500000
    int kk = out_size / DIM;         // 2048

    zero_kernel<<<256, 256>>>();
    int score_blocks = (n + 7) / 8;  // 8 warps (rows) per 256-thread block
    score_kernel<<<score_blocks, 256>>>(x, p, n);
    thresh_kernel<<<1, 256>>>(kk);
    compact_kernel<<<2048, 256>>>(n);
    sort_kernel<<<1, 1024>>>(kk);
    gather_kernel<<<kk, DIM>>>(x, out);
}